// round 1
// baseline (speedup 1.0000x reference)
#include <cuda_runtime.h>
#include <cuda_bf16.h>
#include <math.h>

// ---------------------------------------------------------------------------
// Problem constants
// ---------------------------------------------------------------------------
#define NB      4
#define CIN     512
#define COUT    512
#define HH      64
#define WW      64
#define NPIX    (HH*WW)            // 4096
#define NANCH   9
#define NA      (NPIX*NANCH)       // 36864
#define NPRE    6000
#define NPOST   300
#define NEG_INF (-1e30f)

// output layout (flatten of (rpn_locs, rpn_scores, rois, anchor))
#define OFF_LOCS    0
#define OFF_SCORES  (NB*NA*4)                    // 589824
#define OFF_ROIS    (OFF_SCORES + NB*NA*2)       // 884736
#define OFF_ANCHOR  (OFF_ROIS + NB*NPOST*4)      // 889536

// ---------------------------------------------------------------------------
// Device scratch (static; no allocations allowed)
// ---------------------------------------------------------------------------
__device__ float    g_feat[(size_t)NB*CIN*NPIX];     // 33.5 MB
__device__ float    g_fg[NB*NA];
__device__ float    g_msc[NB*NA];
__device__ unsigned g_keys[NB*NA];
__device__ float4   g_roisAll[NB*NA];
__device__ float4   g_cboxes[NB*NPRE];
__device__ float    g_cscores[NB*NPRE];
__device__ unsigned g_thr[NB];
__device__ int      g_tieneed[NB];
__device__ int      g_ctrG[NB];
__device__ int      g_ctrT[NB];

// ---------------------------------------------------------------------------
// Kernel 1: 3x3 conv (512->512, pad 1) + bias + ReLU.
// Block: 256 threads = 16x16. Tile: 64 out-channels x 64 pixels (one row).
// Each thread: 4 oc x 4 px accumulators. K loop over 8-ic chunks.
// ---------------------------------------------------------------------------
__global__ __launch_bounds__(256)
void conv3x3_kernel(const float* __restrict__ x,
                    const float* __restrict__ w,
                    const float* __restrict__ b)
{
    const int y   = blockIdx.x;          // row 0..63
    const int ocg = blockIdx.y;          // oc group 0..7
    const int n   = blockIdx.z;          // batch
    const int tid = threadIdx.x;
    const int tx  = tid & 15;
    const int ty  = tid >> 4;
    const int oc0 = ocg * 64;

    __shared__ float sIn[8][3][66];      // [ic][ky][col+1], zero padded
    __shared__ float sW[64][73];         // [oc][ic*9 + k], pad 73 vs bank conflicts

    float acc[4][4];
#pragma unroll
    for (int i = 0; i < 4; i++)
#pragma unroll
        for (int j = 0; j < 4; j++) acc[i][j] = 0.f;

    for (int ic0 = 0; ic0 < CIN; ic0 += 8) {
        // load input halo rows y-1..y+1 for 8 ic
        for (int i = tid; i < 8 * 3 * 66; i += 256) {
            int ic = i / 198; int rem = i % 198;
            int r = rem / 66; int c = rem % 66;
            int gy = y + r - 1, gx = c - 1;
            float v = 0.f;
            if ((unsigned)gy < 64u && (unsigned)gx < 64u)
                v = x[(((size_t)n * CIN + ic0 + ic) * 64 + gy) * 64 + gx];
            sIn[ic][r][c] = v;
        }
        // load weights: 64 oc x (8 ic x 9)
        for (int i = tid; i < 64 * 72; i += 256) {
            int oc = i / 72; int k = i % 72;
            sW[oc][k] = w[(((size_t)(oc0 + oc)) * CIN + ic0 + (k / 9)) * 9 + (k % 9)];
        }
        __syncthreads();

#pragma unroll
        for (int ic = 0; ic < 8; ic++) {
#pragma unroll
            for (int ky = 0; ky < 3; ky++) {
                float a[6];
#pragma unroll
                for (int m = 0; m < 6; m++) a[m] = sIn[ic][ky][tx * 4 + m];
#pragma unroll
                for (int oo = 0; oo < 4; oo++) {
                    float w0 = sW[ty * 4 + oo][ic * 9 + ky * 3 + 0];
                    float w1 = sW[ty * 4 + oo][ic * 9 + ky * 3 + 1];
                    float w2 = sW[ty * 4 + oo][ic * 9 + ky * 3 + 2];
#pragma unroll
                    for (int j = 0; j < 4; j++)
                        acc[oo][j] += a[j] * w0 + a[j + 1] * w1 + a[j + 2] * w2;
                }
            }
        }
        __syncthreads();
    }

#pragma unroll
    for (int oo = 0; oo < 4; oo++) {
        int oc = oc0 + ty * 4 + oo;
        float bias = b[oc];
#pragma unroll
        for (int j = 0; j < 4; j++) {
            float v = acc[oo][j] + bias;
            v = v > 0.f ? v : 0.f;
            g_feat[(((size_t)n * COUT + oc) * 64 + y) * 64 + tx * 4 + j] = v;
        }
    }
}

// ---------------------------------------------------------------------------
// Kernel 2: fused 1x1 heads. Combined channels: [0..35] loc, [36..53] score,
// pad to 64. Writes transposed rpn_locs/rpn_scores into d_out, fg sigmoid to
// g_fg.
// ---------------------------------------------------------------------------
__global__ __launch_bounds__(256)
void head_kernel(const float* __restrict__ sw, const float* __restrict__ sb,
                 const float* __restrict__ lw, const float* __restrict__ lb,
                 float* __restrict__ d_out)
{
    const int y   = blockIdx.x;
    const int n   = blockIdx.y;
    const int tid = threadIdx.x;
    const int tx  = tid & 15;
    const int ty  = tid >> 4;

    __shared__ float sF[16][64];
    __shared__ float sWc[64][17];

    float acc[4][4];
#pragma unroll
    for (int i = 0; i < 4; i++)
#pragma unroll
        for (int j = 0; j < 4; j++) acc[i][j] = 0.f;

    for (int ic0 = 0; ic0 < CIN; ic0 += 16) {
        for (int i = tid; i < 16 * 64; i += 256) {
            int ic = i >> 6, c = i & 63;
            sF[ic][c] = g_feat[(((size_t)n * CIN + ic0 + ic) * 64 + y) * 64 + c];
        }
        for (int i = tid; i < 64 * 16; i += 256) {
            int o = i >> 4, ic = i & 15;
            float v = 0.f;
            if (o < 36)       v = lw[(size_t)o * CIN + ic0 + ic];
            else if (o < 54)  v = sw[(size_t)(o - 36) * CIN + ic0 + ic];
            sWc[o][ic] = v;
        }
        __syncthreads();
#pragma unroll
        for (int ic = 0; ic < 16; ic++) {
            float a0 = sF[ic][tx * 4 + 0];
            float a1 = sF[ic][tx * 4 + 1];
            float a2 = sF[ic][tx * 4 + 2];
            float a3 = sF[ic][tx * 4 + 3];
#pragma unroll
            for (int oo = 0; oo < 4; oo++) {
                float wv = sWc[ty * 4 + oo][ic];
                acc[oo][0] += a0 * wv;
                acc[oo][1] += a1 * wv;
                acc[oo][2] += a2 * wv;
                acc[oo][3] += a3 * wv;
            }
        }
        __syncthreads();
    }

    const int obase = ty * 4;
#pragma unroll
    for (int oo = 0; oo < 4; oo++) {
        int o = obase + oo;
        if (o < 36) {
            int a = o >> 2, j = o & 3;
            float bias = lb[o];
#pragma unroll
            for (int jj = 0; jj < 4; jj++) {
                int p = y * 64 + tx * 4 + jj;
                d_out[OFF_LOCS + ((size_t)(n * NA + p * 9 + a)) * 4 + j] = acc[oo][jj] + bias;
            }
        } else if (o < 54) {
            int q = o - 36, a = q >> 1, t = q & 1;
            float bias = sb[q];
#pragma unroll
            for (int jj = 0; jj < 4; jj++) {
                int p = y * 64 + tx * 4 + jj;
                d_out[OFF_SCORES + ((size_t)(n * NA + p * 9 + a)) * 2 + t] = acc[oo][jj] + bias;
            }
        }
    }
    // fg = softmax(...)[:,1] = sigmoid(s1 - s0); pairs are within this thread
    if (obase >= 36 && obase < 54) {
#pragma unroll
        for (int pair = 0; pair < 2; pair++) {
            int o = obase + pair * 2;
            if (o < 54) {
                int q = o - 36, a = q >> 1;
                float b0 = sb[q], b1 = sb[q + 1];
#pragma unroll
                for (int jj = 0; jj < 4; jj++) {
                    float s0 = acc[pair * 2][jj] + b0;
                    float s1 = acc[pair * 2 + 1][jj] + b1;
                    float fg = 1.f / (1.f + expf(s0 - s1));
                    int p = y * 64 + tx * 4 + jj;
                    g_fg[(size_t)n * NA + p * 9 + a] = fg;
                }
            }
        }
    }
}

// ---------------------------------------------------------------------------
// Kernel 3: anchors + loc2bbox + clip + min-size mask + sortable keys.
// Also writes the anchor output block (batch 0 threads).
// ---------------------------------------------------------------------------
__global__ void boxes_kernel(const int* __restrict__ imgh, const int* __restrict__ imgw,
                             float* __restrict__ d_out)
{
    int g = blockIdx.x * blockDim.x + threadIdx.x;
    if (g >= NB * NA) return;
    int n = g / NA, i = g % NA;
    int p = i / 9, a = i % 9;
    int r = a / 3, s = a % 3;

    const float rat[3] = {0.5f, 1.f, 2.f};
    const float scl[3] = {8.f, 16.f, 32.f};
    float hh = 16.f * scl[s] * sqrtf(rat[r]);
    float ww = 16.f * scl[s] * sqrtf(1.f / rat[r]);
    float shy = (float)(p >> 6) * 16.f;
    float shx = (float)(p & 63) * 16.f;
    float b0 = 8.f - 0.5f * hh, b1 = 8.f - 0.5f * ww;
    float b2 = 8.f + 0.5f * hh, b3 = 8.f + 0.5f * ww;
    float ay0 = shy + b0, ax0 = shx + b1, ay1 = shy + b2, ax1 = shx + b3;

    if (n == 0) {
        d_out[OFF_ANCHOR + (size_t)i * 4 + 0] = ay0;
        d_out[OFF_ANCHOR + (size_t)i * 4 + 1] = ax0;
        d_out[OFF_ANCHOR + (size_t)i * 4 + 2] = ay1;
        d_out[OFF_ANCHOR + (size_t)i * 4 + 3] = ax1;
    }

    float ha = ay1 - ay0, wa = ax1 - ax0;
    float cy = ay0 + 0.5f * ha, cx = ax0 + 0.5f * wa;

    const float* lc = d_out + OFF_LOCS + (size_t)g * 4;
    float dy = lc[0], dx = lc[1], dh = lc[2], dw = lc[3];

    float ncy = dy * ha + cy;
    float ncx = dx * wa + cx;
    float nh  = expf(dh) * ha;
    float nw  = expf(dw) * wa;

    float Hc = (float)(*imgh), Wc = (float)(*imgw);
    float y0 = fminf(fmaxf(ncy - 0.5f * nh, 0.f), Hc);
    float x0 = fminf(fmaxf(ncx - 0.5f * nw, 0.f), Wc);
    float y1 = fminf(fmaxf(ncy + 0.5f * nh, 0.f), Hc);
    float x1 = fminf(fmaxf(ncx + 0.5f * nw, 0.f), Wc);

    float hs = y1 - y0, ws = x1 - x0;
    bool valid = (hs >= 16.f) && (ws >= 16.f);
    float sc = valid ? g_fg[g] : NEG_INF;
    g_msc[g] = sc;

    unsigned u = __float_as_uint(sc);
    u = (u & 0x80000000u) ? ~u : (u | 0x80000000u);
    g_keys[g] = u;
    g_roisAll[g] = make_float4(y0, x0, y1, x1);
}

// ---------------------------------------------------------------------------
// Kernel 4: 4-pass radix select: exact threshold key for top-6000 per batch.
// ---------------------------------------------------------------------------
__global__ void radix_kernel()
{
    const int n = blockIdx.x;
    const unsigned* kk = g_keys + (size_t)n * NA;
    __shared__ unsigned hist[256];
    __shared__ unsigned s_prefix;
    __shared__ int s_k;

    unsigned prefix = 0, mask = 0;
    int k = NPRE;

    for (int pass = 0; pass < 4; pass++) {
        int shift = 24 - pass * 8;
        hist[threadIdx.x] = 0;
        __syncthreads();
        for (int i = threadIdx.x; i < NA; i += 256) {
            unsigned u = kk[i];
            if ((u & mask) == prefix) atomicAdd(&hist[(u >> shift) & 255], 1u);
        }
        __syncthreads();
        if (threadIdx.x == 0) {
            int rem = k, d = 255;
            for (; d > 0; d--) {
                int c = (int)hist[d];
                if (rem > c) rem -= c; else break;
            }
            s_prefix = prefix | ((unsigned)d << shift);
            s_k = rem;
        }
        __syncthreads();
        prefix = s_prefix; k = s_k;
        mask |= (0xFFu << shift);
        __syncthreads();
    }
    if (threadIdx.x == 0) {
        g_thr[n] = prefix;       // exact key of the 6000th largest
        g_tieneed[n] = k;        // how many of the ==thr keys to take
        g_ctrG[n] = 0;
        g_ctrT[n] = 0;
    }
}

// ---------------------------------------------------------------------------
// Kernel 5: compact the top-6000 set (boxes + scores) per batch.
// ---------------------------------------------------------------------------
__global__ void compact_kernel()
{
    int g = blockIdx.x * blockDim.x + threadIdx.x;
    if (g >= NB * NA) return;
    int n = g / NA;
    unsigned T = g_thr[n];
    unsigned u = g_keys[g];
    int slot = -1;
    if (u > T) {
        slot = atomicAdd(&g_ctrG[n], 1);
    } else if (u == T) {
        int p2 = atomicAdd(&g_ctrT[n], 1);
        int tn = g_tieneed[n];
        if (p2 < tn) slot = (NPRE - tn) + p2;
    }
    if (slot >= 0) {
        g_cscores[(size_t)n * NPRE + slot] = g_msc[g];
        g_cboxes[(size_t)n * NPRE + slot]  = g_roisAll[g];
    }
}

// ---------------------------------------------------------------------------
// Kernel 6: fixed-iteration NMS (300 picks over 6000 candidates) + roi output.
// One block per batch, 1024 threads. Scores in smem, boxes via L1.
// ---------------------------------------------------------------------------
__global__ __launch_bounds__(1024)
void nms_kernel(float* __restrict__ d_out)
{
    const int n = blockIdx.x;
    const int tid = threadIdx.x;
    __shared__ float ssc[NPRE];
    __shared__ int   skeep[NPOST];
    __shared__ float rv[32];
    __shared__ int   ri[32];
    __shared__ int   sbi;
    __shared__ float sbv;

    const float4* cb = g_cboxes + (size_t)n * NPRE;

    for (int j = tid; j < NPRE; j += 1024) ssc[j] = g_cscores[(size_t)n * NPRE + j];
    __syncthreads();

    for (int it = 0; it < NPOST; it++) {
        // argmax, tie-break lowest index (matches jnp.argmax)
        float bv = -3e38f; int bi = 0x7FFFFFFF;
        for (int j = tid; j < NPRE; j += 1024) {
            float v = ssc[j];
            if (v > bv) { bv = v; bi = j; }
        }
#pragma unroll
        for (int o = 16; o; o >>= 1) {
            float ov = __shfl_down_sync(0xFFFFFFFFu, bv, o);
            int   oi = __shfl_down_sync(0xFFFFFFFFu, bi, o);
            if (ov > bv || (ov == bv && oi < bi)) { bv = ov; bi = oi; }
        }
        if ((tid & 31) == 0) { rv[tid >> 5] = bv; ri[tid >> 5] = bi; }
        __syncthreads();
        if (tid < 32) {
            bv = rv[tid]; bi = ri[tid];
#pragma unroll
            for (int o = 16; o; o >>= 1) {
                float ov = __shfl_down_sync(0xFFFFFFFFu, bv, o);
                int   oi = __shfl_down_sync(0xFFFFFFFFu, bi, o);
                if (ov > bv || (ov == bv && oi < bi)) { bv = ov; bi = oi; }
            }
            if (tid == 0) { sbi = bi; sbv = bv; }
        }
        __syncthreads();
        const int   idx = sbi;
        const float val = sbv;
        if (tid == 0) skeep[it] = (val > NEG_INF * 0.5f) ? idx : -1;

        float4 B = __ldg((const float4*)&cb[idx]);
        float aB = (B.z - B.x) * (B.w - B.y);

        for (int j = tid; j < NPRE; j += 1024) {
            float4 c = cb[j];
            float tyv = fmaxf(B.x, c.x);
            float txv = fmaxf(B.y, c.y);
            float byv = fminf(B.z, c.z);
            float bxv = fminf(B.w, c.w);
            float ih = fmaxf(byv - tyv, 0.f);
            float iw = fmaxf(bxv - txv, 0.f);
            float inter = ih * iw;
            float a2 = (c.z - c.x) * (c.w - c.y);
            float iou = inter / fmaxf(aB + a2 - inter, 1e-6f);
            if (iou > 0.7f) ssc[j] = NEG_INF;
        }
        if (tid == 0) ssc[idx] = NEG_INF;
        __syncthreads();
    }

    for (int i = tid; i < NPOST; i += 1024) {
        int k2 = skeep[i];
        float4 o = make_float4(0.f, 0.f, 0.f, 0.f);
        if (k2 >= 0) o = cb[k2];
        *(float4*)(d_out + OFF_ROIS + ((size_t)(n * NPOST + i)) * 4) = o;
    }
}

// ---------------------------------------------------------------------------
// launch
// ---------------------------------------------------------------------------
extern "C" void kernel_launch(void* const* d_in, const int* in_sizes, int n_in,
                              void* d_out, int out_size)
{
    const float* x   = (const float*)d_in[0];
    const float* c1w = (const float*)d_in[1];
    const float* c1b = (const float*)d_in[2];
    const float* sw  = (const float*)d_in[3];
    const float* sb  = (const float*)d_in[4];
    const float* lw  = (const float*)d_in[5];
    const float* lb  = (const float*)d_in[6];
    const int*   ih  = (const int*)d_in[7];
    const int*   iw  = (const int*)d_in[8];
    float* out = (float*)d_out;

    conv3x3_kernel<<<dim3(HH, COUT / 64, NB), 256>>>(x, c1w, c1b);
    head_kernel<<<dim3(HH, NB), 256>>>(sw, sb, lw, lb, out);
    boxes_kernel<<<(NB * NA + 255) / 256, 256>>>(ih, iw, out);
    radix_kernel<<<NB, 256>>>();
    compact_kernel<<<(NB * NA + 255) / 256, 256>>>();
    nms_kernel<<<NB, 1024>>>(out);
}

// round 6
// speedup vs baseline: 1.0067x; 1.0067x over previous
#include <cuda_runtime.h>
#include <cuda_bf16.h>
#include <math.h>
#include <stdint.h>

// ---------------------------------------------------------------------------
// Problem constants
// ---------------------------------------------------------------------------
#define NB      4
#define CIN     512
#define COUT    512
#define HH      64
#define WW      64
#define NPIX    (HH*WW)            // 4096
#define NANCH   9
#define NA      (NPIX*NANCH)       // 36864
#define NPRE    6000
#define NPOST   300
#define NEG_INF (-1e30f)

// output layout (flatten of (rpn_locs, rpn_scores, rois, anchor))
#define OFF_LOCS    0
#define OFF_SCORES  (NB*NA*4)                    // 589824
#define OFF_ROIS    (OFF_SCORES + NB*NA*2)       // 884736
#define OFF_ANCHOR  (OFF_ROIS + NB*NPOST*4)      // 889536

// ---------------------------------------------------------------------------
// Device scratch
// ---------------------------------------------------------------------------
__device__ float    g_feat[(size_t)NB*CIN*NPIX];      // 33.5 MB
__device__ float    g_xt_h[(size_t)NB*NPIX*CIN];
__device__ float    g_xt_m[(size_t)NB*NPIX*CIN];
__device__ float    g_xt_l[(size_t)NB*NPIX*CIN];
__device__ float    g_wp_h[(size_t)9*COUT*CIN];
__device__ float    g_wp_m[(size_t)9*COUT*CIN];
__device__ float    g_wp_l[(size_t)9*COUT*CIN];
__device__ float    g_fg[NB*NA];
__device__ float    g_msc[NB*NA];
__device__ unsigned g_keys[NB*NA];
__device__ float4   g_roisAll[NB*NA];
__device__ float4   g_cboxes[NB*NPRE];
__device__ float    g_cscores[NB*NPRE];
__device__ unsigned g_thr[NB];
__device__ int      g_tieneed[NB];
__device__ int      g_ctrG[NB];
__device__ int      g_ctrT[NB];

// ---------------------------------------------------------------------------
// helpers
// ---------------------------------------------------------------------------
__device__ __forceinline__ uint32_t smem_u32(const void* p) {
    uint32_t a;
    asm("{ .reg .u64 t; cvta.to.shared.u64 t, %1; cvt.u32.u64 %0, t; }" : "=r"(a) : "l"(p));
    return a;
}
__device__ __forceinline__ float tf32_rna_f(float v) {
    uint32_t u; asm("cvt.rna.tf32.f32 %0, %1;" : "=r"(u) : "f"(v));
    return __uint_as_float(u);
}
__device__ __forceinline__ void mma1688(float* c, const uint32_t* a, const uint32_t* b) {
    asm volatile(
        "mma.sync.aligned.m16n8k8.row.col.f32.tf32.tf32.f32 "
        "{%0,%1,%2,%3}, {%4,%5,%6,%7}, {%8,%9}, {%0,%1,%2,%3};"
        : "+f"(c[0]), "+f"(c[1]), "+f"(c[2]), "+f"(c[3])
        : "r"(a[0]), "r"(a[1]), "r"(a[2]), "r"(a[3]), "r"(b[0]), "r"(b[1]));
}

// ---------------------------------------------------------------------------
// Prep A: transpose x [n][c][p] -> g_xt_{h,m,l} [n][p][c] (3-way tf32 split)
// ---------------------------------------------------------------------------
__global__ void transpose_x_kernel(const float* __restrict__ x)
{
    __shared__ float t[32][33];
    const int n  = blockIdx.z;
    const int p0 = blockIdx.x * 32;
    const int c0 = blockIdx.y * 32;
    const int tx = threadIdx.x, ty = threadIdx.y;
#pragma unroll
    for (int j = 0; j < 32; j += 8)
        t[ty + j][tx] = x[((size_t)n * CIN + c0 + ty + j) * NPIX + p0 + tx];
    __syncthreads();
#pragma unroll
    for (int j = 0; j < 32; j += 8) {
        float v = t[tx][ty + j];
        float h = tf32_rna_f(v);
        float r = v - h;
        float m = tf32_rna_f(r);
        float l = tf32_rna_f(r - m);
        size_t o = ((size_t)n * NPIX + p0 + ty + j) * CIN + c0 + tx;
        g_xt_h[o] = h;
        g_xt_m[o] = m;
        g_xt_l[o] = l;
    }
}

// ---------------------------------------------------------------------------
// Prep B: pack w [oc][ic][3][3] -> g_wp_{h,m,l} [tap][oc][ic]
// ---------------------------------------------------------------------------
__global__ void pack_w_kernel(const float* __restrict__ w)
{
    int idx = blockIdx.x * 256 + threadIdx.x;   // oc*512 + ic
    if (idx >= COUT * CIN) return;
    const float* src = w + (size_t)idx * 9;
#pragma unroll
    for (int t = 0; t < 9; t++) {
        float v = src[t];
        float h = tf32_rna_f(v);
        float r = v - h;
        float m = tf32_rna_f(r);
        float l = tf32_rna_f(r - m);
        size_t o = (size_t)t * COUT * CIN + idx;
        g_wp_h[o] = h;
        g_wp_m[o] = m;
        g_wp_l[o] = l;
    }
}

// ---------------------------------------------------------------------------
// Conv via tf32x6 mma.sync implicit GEMM with TWO-LEVEL ACCUMULATION:
//   acc_main += ah*bh
//   acc_corr += am*bm + ah*bl + al*bh + ah*bm + am*bh
// Final: acc_main + acc_corr (corrections no longer swallowed by main's ulp).
// CTA: 256 thr (8 warps, 2x4). Tile 128 oc x 128 px. K: 288 chunks of 16 ic.
// ---------------------------------------------------------------------------
#define ASTRIDE 20
#define TILE_F  (128 * ASTRIDE)
#define STAGE_F (6 * TILE_F)
#define CONV_SMEM (2 * STAGE_F * 4)

__device__ __forceinline__ void conv_load_chunk(float* sm, int c, int s,
                                                int p0, int ocb, int n, int tid)
{
    const int tap = c >> 5;            // 32 chunks of 16 per tap
    const int ic0 = (c & 31) << 4;
    const int dy = tap / 3 - 1, dx = tap % 3 - 1;
    float* st = sm + s * STAGE_F;

    // A tiles: 128 oc x 16 ic, 3 splits
#pragma unroll
    for (int k = 0; k < 2; k++) {
        int cid = tid + k * 256;
        int row = cid >> 2, c4 = cid & 3;
        size_t go = ((size_t)tap * COUT + ocb + row) * CIN + ic0 + c4 * 4;
        uint32_t o = (uint32_t)(row * ASTRIDE + c4 * 4);
        uint32_t sh = smem_u32(st + 0 * TILE_F + o);
        uint32_t sm_ = smem_u32(st + 1 * TILE_F + o);
        uint32_t sl = smem_u32(st + 2 * TILE_F + o);
        asm volatile("cp.async.cg.shared.global [%0], [%1], 16;" :: "r"(sh),  "l"(g_wp_h + go));
        asm volatile("cp.async.cg.shared.global [%0], [%1], 16;" :: "r"(sm_), "l"(g_wp_m + go));
        asm volatile("cp.async.cg.shared.global [%0], [%1], 16;" :: "r"(sl),  "l"(g_wp_l + go));
    }
    // B tiles: 128 px x 16 ic, shifted, zero-filled at borders, 3 splits
#pragma unroll
    for (int k = 0; k < 2; k++) {
        int cid = tid + k * 256;
        int row = cid >> 2, c4 = cid & 3;
        int p = p0 + row;
        int ys = (p >> 6) + dy, xs = (p & 63) + dx;
        bool valid = ((unsigned)ys < 64u) && ((unsigned)xs < 64u);
        int srow = valid ? (ys * 64 + xs) : 0;
        size_t go = ((size_t)n * NPIX + srow) * CIN + ic0 + c4 * 4;
        unsigned sz = valid ? 16u : 0u;
        uint32_t o = (uint32_t)(row * ASTRIDE + c4 * 4);
        uint32_t sh = smem_u32(st + 3 * TILE_F + o);
        uint32_t sm_ = smem_u32(st + 4 * TILE_F + o);
        uint32_t sl = smem_u32(st + 5 * TILE_F + o);
        asm volatile("cp.async.cg.shared.global [%0], [%1], 16, %2;" :: "r"(sh),  "l"(g_xt_h + go), "r"(sz));
        asm volatile("cp.async.cg.shared.global [%0], [%1], 16, %2;" :: "r"(sm_), "l"(g_xt_m + go), "r"(sz));
        asm volatile("cp.async.cg.shared.global [%0], [%1], 16, %2;" :: "r"(sl),  "l"(g_xt_l + go), "r"(sz));
    }
    asm volatile("cp.async.commit_group;");
}

__global__ __launch_bounds__(256)
void conv_mma_kernel(const float* __restrict__ bias)
{
    extern __shared__ float sm[];
    const int tid = threadIdx.x;
    const int p0  = blockIdx.x * 128;
    const int ocb = blockIdx.y * 128;
    const int n   = blockIdx.z;
    const int w   = tid >> 5;
    const int wr  = w >> 2;          // 0..1
    const int wc  = w & 3;           // 0..3
    const int lane = tid & 31;
    const int grp = lane >> 2;       // 0..7
    const int qid = lane & 3;        // 0..3

    float accM[4][4][4];             // hh (main)
    float accC[4][4][4];             // corrections
#pragma unroll
    for (int mt = 0; mt < 4; mt++)
#pragma unroll
        for (int nt = 0; nt < 4; nt++)
#pragma unroll
            for (int q = 0; q < 4; q++) { accM[mt][nt][q] = 0.f; accC[mt][nt][q] = 0.f; }

    conv_load_chunk(sm, 0, 0, p0, ocb, n, tid);

    for (int i = 0; i < 288; i++) {
        const int s = i & 1;
        asm volatile("cp.async.wait_group 0;" ::: "memory");
        __syncthreads();
        if (i + 1 < 288)
            conv_load_chunk(sm, i + 1, s ^ 1, p0, ocb, n, tid);

        const float* st = sm + s * STAGE_F;
        const float* Ah = st;
        const float* Am = st + TILE_F;
        const float* Al = st + 2 * TILE_F;
        const float* Bh = st + 3 * TILE_F;
        const float* Bm = st + 4 * TILE_F;
        const float* Bl = st + 5 * TILE_F;

#pragma unroll
        for (int ks = 0; ks < 2; ks++) {
            const int kc = ks * 8 + qid;
            uint32_t bfh[4][2], bfm[4][2], bfl[4][2];
#pragma unroll
            for (int nt = 0; nt < 4; nt++) {
                int cl = wc * 32 + nt * 8 + grp;
                int o  = cl * ASTRIDE + kc;
                bfh[nt][0] = __float_as_uint(Bh[o]);
                bfh[nt][1] = __float_as_uint(Bh[o + 4]);
                bfm[nt][0] = __float_as_uint(Bm[o]);
                bfm[nt][1] = __float_as_uint(Bm[o + 4]);
                bfl[nt][0] = __float_as_uint(Bl[o]);
                bfl[nt][1] = __float_as_uint(Bl[o + 4]);
            }
            uint32_t afh[4][4], afx[4][4];
            // Phase 1: afx = A_mid. Terms mm, mh, hm (corr) and hh (main).
#pragma unroll
            for (int mt = 0; mt < 4; mt++) {
                int r0 = wr * 64 + mt * 16 + grp;
                int o0 = r0 * ASTRIDE + kc;
                int o1 = (r0 + 8) * ASTRIDE + kc;
                afh[mt][0] = __float_as_uint(Ah[o0]);
                afh[mt][1] = __float_as_uint(Ah[o1]);
                afh[mt][2] = __float_as_uint(Ah[o0 + 4]);
                afh[mt][3] = __float_as_uint(Ah[o1 + 4]);
                afx[mt][0] = __float_as_uint(Am[o0]);
                afx[mt][1] = __float_as_uint(Am[o1]);
                afx[mt][2] = __float_as_uint(Am[o0 + 4]);
                afx[mt][3] = __float_as_uint(Am[o1 + 4]);
            }
#pragma unroll
            for (int mt = 0; mt < 4; mt++)
#pragma unroll
                for (int nt = 0; nt < 4; nt++) {
                    mma1688(accC[mt][nt], afx[mt], bfm[nt]);   // mm
                    mma1688(accC[mt][nt], afx[mt], bfh[nt]);   // mh
                    mma1688(accC[mt][nt], afh[mt], bfm[nt]);   // hm
                    mma1688(accM[mt][nt], afh[mt], bfh[nt]);   // hh
                }
            // Phase 2: afx = A_low. Terms lh, hl (corr).
#pragma unroll
            for (int mt = 0; mt < 4; mt++) {
                int r0 = wr * 64 + mt * 16 + grp;
                int o0 = r0 * ASTRIDE + kc;
                int o1 = (r0 + 8) * ASTRIDE + kc;
                afx[mt][0] = __float_as_uint(Al[o0]);
                afx[mt][1] = __float_as_uint(Al[o1]);
                afx[mt][2] = __float_as_uint(Al[o0 + 4]);
                afx[mt][3] = __float_as_uint(Al[o1 + 4]);
            }
#pragma unroll
            for (int mt = 0; mt < 4; mt++)
#pragma unroll
                for (int nt = 0; nt < 4; nt++) {
                    mma1688(accC[mt][nt], afx[mt], bfh[nt]);   // lh
                    mma1688(accC[mt][nt], afh[mt], bfl[nt]);   // hl
                }
        }
        __syncthreads();
    }

    // epilogue: main + corr + bias, relu, write g_feat [n][oc][px]
#pragma unroll
    for (int mt = 0; mt < 4; mt++) {
        int r0 = ocb + wr * 64 + mt * 16 + grp;
        int r1 = r0 + 8;
        float b0 = bias[r0], b1 = bias[r1];
        float* d0 = g_feat + ((size_t)n * COUT + r0) * NPIX + p0;
        float* d1 = g_feat + ((size_t)n * COUT + r1) * NPIX + p0;
#pragma unroll
        for (int nt = 0; nt < 4; nt++) {
            int col = wc * 32 + nt * 8 + qid * 2;
            float2 v0, v1;
            v0.x = fmaxf((accM[mt][nt][0] + accC[mt][nt][0]) + b0, 0.f);
            v0.y = fmaxf((accM[mt][nt][1] + accC[mt][nt][1]) + b0, 0.f);
            v1.x = fmaxf((accM[mt][nt][2] + accC[mt][nt][2]) + b1, 0.f);
            v1.y = fmaxf((accM[mt][nt][3] + accC[mt][nt][3]) + b1, 0.f);
            *(float2*)(d0 + col) = v0;
            *(float2*)(d1 + col) = v1;
        }
    }
}

// ---------------------------------------------------------------------------
// Kernel 2: fused 1x1 heads
// ---------------------------------------------------------------------------
__global__ __launch_bounds__(256)
void head_kernel(const float* __restrict__ sw, const float* __restrict__ sb,
                 const float* __restrict__ lw, const float* __restrict__ lb,
                 float* __restrict__ d_out)
{
    const int y   = blockIdx.x;
    const int n   = blockIdx.y;
    const int tid = threadIdx.x;
    const int tx  = tid & 15;
    const int ty  = tid >> 4;

    __shared__ float sF[16][64];
    __shared__ float sWc[64][17];

    float acc[4][4];
#pragma unroll
    for (int i = 0; i < 4; i++)
#pragma unroll
        for (int j = 0; j < 4; j++) acc[i][j] = 0.f;

    for (int ic0 = 0; ic0 < CIN; ic0 += 16) {
        for (int i = tid; i < 16 * 64; i += 256) {
            int ic = i >> 6, c = i & 63;
            sF[ic][c] = g_feat[(((size_t)n * CIN + ic0 + ic) * 64 + y) * 64 + c];
        }
        for (int i = tid; i < 64 * 16; i += 256) {
            int o = i >> 4, ic = i & 15;
            float v = 0.f;
            if (o < 36)       v = lw[(size_t)o * CIN + ic0 + ic];
            else if (o < 54)  v = sw[(size_t)(o - 36) * CIN + ic0 + ic];
            sWc[o][ic] = v;
        }
        __syncthreads();
#pragma unroll
        for (int ic = 0; ic < 16; ic++) {
            float a0 = sF[ic][tx * 4 + 0];
            float a1 = sF[ic][tx * 4 + 1];
            float a2 = sF[ic][tx * 4 + 2];
            float a3 = sF[ic][tx * 4 + 3];
#pragma unroll
            for (int oo = 0; oo < 4; oo++) {
                float wv = sWc[ty * 4 + oo][ic];
                acc[oo][0] += a0 * wv;
                acc[oo][1] += a1 * wv;
                acc[oo][2] += a2 * wv;
                acc[oo][3] += a3 * wv;
            }
        }
        __syncthreads();
    }

    const int obase = ty * 4;
#pragma unroll
    for (int oo = 0; oo < 4; oo++) {
        int o = obase + oo;
        if (o < 36) {
            int a = o >> 2, j = o & 3;
            float bias = lb[o];
#pragma unroll
            for (int jj = 0; jj < 4; jj++) {
                int p = y * 64 + tx * 4 + jj;
                d_out[OFF_LOCS + ((size_t)(n * NA + p * 9 + a)) * 4 + j] = acc[oo][jj] + bias;
            }
        } else if (o < 54) {
            int q = o - 36, a = q >> 1, t = q & 1;
            float bias = sb[q];
#pragma unroll
            for (int jj = 0; jj < 4; jj++) {
                int p = y * 64 + tx * 4 + jj;
                d_out[OFF_SCORES + ((size_t)(n * NA + p * 9 + a)) * 2 + t] = acc[oo][jj] + bias;
            }
        }
    }
    if (obase >= 36 && obase < 54) {
#pragma unroll
        for (int pair = 0; pair < 2; pair++) {
            int o = obase + pair * 2;
            if (o < 54) {
                int q = o - 36, a = q >> 1;
                float b0 = sb[q], b1 = sb[q + 1];
#pragma unroll
                for (int jj = 0; jj < 4; jj++) {
                    float s0 = acc[pair * 2][jj] + b0;
                    float s1 = acc[pair * 2 + 1][jj] + b1;
                    float fg = 1.f / (1.f + expf(s0 - s1));
                    int p = y * 64 + tx * 4 + jj;
                    g_fg[(size_t)n * NA + p * 9 + a] = fg;
                }
            }
        }
    }
}

// ---------------------------------------------------------------------------
// Kernel 3: anchors + loc2bbox + clip + min-size + keys
// ---------------------------------------------------------------------------
__global__ void boxes_kernel(const int* __restrict__ imgh, const int* __restrict__ imgw,
                             float* __restrict__ d_out)
{
    int g = blockIdx.x * blockDim.x + threadIdx.x;
    if (g >= NB * NA) return;
    int n = g / NA, i = g % NA;
    int p = i / 9, a = i % 9;
    int r = a / 3, s = a % 3;

    const float rat[3] = {0.5f, 1.f, 2.f};
    const float scl[3] = {8.f, 16.f, 32.f};
    float hh = 16.f * scl[s] * sqrtf(rat[r]);
    float ww = 16.f * scl[s] * sqrtf(1.f / rat[r]);
    float shy = (float)(p >> 6) * 16.f;
    float shx = (float)(p & 63) * 16.f;
    float ay0 = shy + 8.f - 0.5f * hh, ax0 = shx + 8.f - 0.5f * ww;
    float ay1 = shy + 8.f + 0.5f * hh, ax1 = shx + 8.f + 0.5f * ww;

    if (n == 0) {
        d_out[OFF_ANCHOR + (size_t)i * 4 + 0] = ay0;
        d_out[OFF_ANCHOR + (size_t)i * 4 + 1] = ax0;
        d_out[OFF_ANCHOR + (size_t)i * 4 + 2] = ay1;
        d_out[OFF_ANCHOR + (size_t)i * 4 + 3] = ax1;
    }

    float ha = ay1 - ay0, wa = ax1 - ax0;
    float cy = ay0 + 0.5f * ha, cx = ax0 + 0.5f * wa;

    const float* lc = d_out + OFF_LOCS + (size_t)g * 4;
    float dy = lc[0], dx = lc[1], dh = lc[2], dw = lc[3];

    float ncy = dy * ha + cy;
    float ncx = dx * wa + cx;
    float nh  = expf(dh) * ha;
    float nw  = expf(dw) * wa;

    float Hc = (float)(*imgh), Wc = (float)(*imgw);
    float y0 = fminf(fmaxf(ncy - 0.5f * nh, 0.f), Hc);
    float x0 = fminf(fmaxf(ncx - 0.5f * nw, 0.f), Wc);
    float y1 = fminf(fmaxf(ncy + 0.5f * nh, 0.f), Hc);
    float x1 = fminf(fmaxf(ncx + 0.5f * nw, 0.f), Wc);

    float hs = y1 - y0, ws = x1 - x0;
    bool valid = (hs >= 16.f) && (ws >= 16.f);
    float sc = valid ? g_fg[g] : NEG_INF;
    g_msc[g] = sc;

    unsigned u = __float_as_uint(sc);
    u = (u & 0x80000000u) ? ~u : (u | 0x80000000u);
    g_keys[g] = u;
    g_roisAll[g] = make_float4(y0, x0, y1, x1);
}

// ---------------------------------------------------------------------------
// Kernel 4: radix select
// ---------------------------------------------------------------------------
__global__ void radix_kernel()
{
    const int n = blockIdx.x;
    const unsigned* kk = g_keys + (size_t)n * NA;
    __shared__ unsigned hist[256];
    __shared__ unsigned s_prefix;
    __shared__ int s_k;

    unsigned prefix = 0, mask = 0;
    int k = NPRE;

    for (int pass = 0; pass < 4; pass++) {
        int shift = 24 - pass * 8;
        hist[threadIdx.x] = 0;
        __syncthreads();
        for (int i = threadIdx.x; i < NA; i += 256) {
            unsigned u = kk[i];
            if ((u & mask) == prefix) atomicAdd(&hist[(u >> shift) & 255], 1u);
        }
        __syncthreads();
        if (threadIdx.x == 0) {
            int rem = k, d = 255;
            for (; d > 0; d--) {
                int c = (int)hist[d];
                if (rem > c) rem -= c; else break;
            }
            s_prefix = prefix | ((unsigned)d << shift);
            s_k = rem;
        }
        __syncthreads();
        prefix = s_prefix; k = s_k;
        mask |= (0xFFu << shift);
        __syncthreads();
    }
    if (threadIdx.x == 0) {
        g_thr[n] = prefix;
        g_tieneed[n] = k;
        g_ctrG[n] = 0;
        g_ctrT[n] = 0;
    }
}

// ---------------------------------------------------------------------------
// Kernel 5: compact top-6000
// ---------------------------------------------------------------------------
__global__ void compact_kernel()
{
    int g = blockIdx.x * blockDim.x + threadIdx.x;
    if (g >= NB * NA) return;
    int n = g / NA;
    unsigned T = g_thr[n];
    unsigned u = g_keys[g];
    int slot = -1;
    if (u > T) {
        slot = atomicAdd(&g_ctrG[n], 1);
    } else if (u == T) {
        int p2 = atomicAdd(&g_ctrT[n], 1);
        int tn = g_tieneed[n];
        if (p2 < tn) slot = (NPRE - tn) + p2;
    }
    if (slot >= 0) {
        g_cscores[(size_t)n * NPRE + slot] = g_msc[g];
        g_cboxes[(size_t)n * NPRE + slot]  = g_roisAll[g];
    }
}

// ---------------------------------------------------------------------------
// Kernel 6: fixed-iteration NMS
// ---------------------------------------------------------------------------
__global__ __launch_bounds__(1024)
void nms_kernel(float* __restrict__ d_out)
{
    const int n = blockIdx.x;
    const int tid = threadIdx.x;
    __shared__ float ssc[NPRE];
    __shared__ int   skeep[NPOST];
    __shared__ float rv[32];
    __shared__ int   ri[32];
    __shared__ int   sbi;
    __shared__ float sbv;

    const float4* cb = g_cboxes + (size_t)n * NPRE;

    for (int j = tid; j < NPRE; j += 1024) ssc[j] = g_cscores[(size_t)n * NPRE + j];
    __syncthreads();

    for (int it = 0; it < NPOST; it++) {
        float bv = -3e38f; int bi = 0x7FFFFFFF;
        for (int j = tid; j < NPRE; j += 1024) {
            float v = ssc[j];
            if (v > bv) { bv = v; bi = j; }
        }
#pragma unroll
        for (int o = 16; o; o >>= 1) {
            float ov = __shfl_down_sync(0xFFFFFFFFu, bv, o);
            int   oi = __shfl_down_sync(0xFFFFFFFFu, bi, o);
            if (ov > bv || (ov == bv && oi < bi)) { bv = ov; bi = oi; }
        }
        if ((tid & 31) == 0) { rv[tid >> 5] = bv; ri[tid >> 5] = bi; }
        __syncthreads();
        if (tid < 32) {
            bv = rv[tid]; bi = ri[tid];
#pragma unroll
            for (int o = 16; o; o >>= 1) {
                float ov = __shfl_down_sync(0xFFFFFFFFu, bv, o);
                int   oi = __shfl_down_sync(0xFFFFFFFFu, bi, o);
                if (ov > bv || (ov == bv && oi < bi)) { bv = ov; bi = oi; }
            }
            if (tid == 0) { sbi = bi; sbv = bv; }
        }
        __syncthreads();
        const int   idx = sbi;
        const float val = sbv;
        if (tid == 0) skeep[it] = (val > NEG_INF * 0.5f) ? idx : -1;

        float4 B = __ldg((const float4*)&cb[idx]);
        float aB = (B.z - B.x) * (B.w - B.y);

        for (int j = tid; j < NPRE; j += 1024) {
            float4 c = cb[j];
            float tyv = fmaxf(B.x, c.x);
            float txv = fmaxf(B.y, c.y);
            float byv = fminf(B.z, c.z);
            float bxv = fminf(B.w, c.w);
            float ih = fmaxf(byv - tyv, 0.f);
            float iw = fmaxf(bxv - txv, 0.f);
            float inter = ih * iw;
            float a2 = (c.z - c.x) * (c.w - c.y);
            float iou = inter / fmaxf(aB + a2 - inter, 1e-6f);
            if (iou > 0.7f) ssc[j] = NEG_INF;
        }
        if (tid == 0) ssc[idx] = NEG_INF;
        __syncthreads();
    }

    for (int i = tid; i < NPOST; i += 1024) {
        int k2 = skeep[i];
        float4 o = make_float4(0.f, 0.f, 0.f, 0.f);
        if (k2 >= 0) o = cb[k2];
        *(float4*)(d_out + OFF_ROIS + ((size_t)(n * NPOST + i)) * 4) = o;
    }
}

// ---------------------------------------------------------------------------
// launch
// ---------------------------------------------------------------------------
extern "C" void kernel_launch(void* const* d_in, const int* in_sizes, int n_in,
                              void* d_out, int out_size)
{
    const float* x   = (const float*)d_in[0];
    const float* c1w = (const float*)d_in[1];
    const float* c1b = (const float*)d_in[2];
    const float* sw  = (const float*)d_in[3];
    const float* sb  = (const float*)d_in[4];
    const float* lw  = (const float*)d_in[5];
    const float* lb  = (const float*)d_in[6];
    const int*   ih  = (const int*)d_in[7];
    const int*   iw  = (const int*)d_in[8];
    float* out = (float*)d_out;

    cudaFuncSetAttribute(conv_mma_kernel,
                         cudaFuncAttributeMaxDynamicSharedMemorySize, CONV_SMEM);

    transpose_x_kernel<<<dim3(NPIX / 32, CIN / 32, NB), dim3(32, 8)>>>(x);
    pack_w_kernel<<<(COUT * CIN) / 256, 256>>>(c1w);
    conv_mma_kernel<<<dim3(32, 4, NB), 256, CONV_SMEM>>>(c1b);
    head_kernel<<<dim3(HH, NB), 256>>>(sw, sb, lw, lb, out);
    boxes_kernel<<<(NB * NA + 255) / 256, 256>>>(ih, iw, out);
    radix_kernel<<<NB, 256>>>();
    compact_kernel<<<(NB * NA + 255) / 256, 256>>>();
    nms_kernel<<<NB, 1024>>>(out);
}

// round 7
// speedup vs baseline: 1.6092x; 1.5985x over previous
#include <cuda_runtime.h>
#include <cuda_bf16.h>
#include <math.h>
#include <stdint.h>

// ---------------------------------------------------------------------------
// Problem constants
// ---------------------------------------------------------------------------
#define NB      4
#define CIN     512
#define COUT    512
#define HH      64
#define WW      64
#define NPIX    (HH*WW)            // 4096
#define NANCH   9
#define NA      (NPIX*NANCH)       // 36864
#define NPRE    6000
#define NPOST   300
#define NEG_INF (-1e30f)

// output layout (flatten of (rpn_locs, rpn_scores, rois, anchor))
#define OFF_LOCS    0
#define OFF_SCORES  (NB*NA*4)                    // 589824
#define OFF_ROIS    (OFF_SCORES + NB*NA*2)       // 884736
#define OFF_ANCHOR  (OFF_ROIS + NB*NPOST*4)      // 889536

// ---------------------------------------------------------------------------
// Device scratch
// ---------------------------------------------------------------------------
__device__ float         g_feat[(size_t)NB*CIN*NPIX];      // 33.5 MB
__device__ __nv_bfloat16 g_xb_h[(size_t)NB*NPIX*CIN];
__device__ __nv_bfloat16 g_xb_m[(size_t)NB*NPIX*CIN];
__device__ __nv_bfloat16 g_xb_l[(size_t)NB*NPIX*CIN];
__device__ __nv_bfloat16 g_wb_h[(size_t)9*COUT*CIN];
__device__ __nv_bfloat16 g_wb_m[(size_t)9*COUT*CIN];
__device__ __nv_bfloat16 g_wb_l[(size_t)9*COUT*CIN];
__device__ float    g_fg[NB*NA];
__device__ float    g_msc[NB*NA];
__device__ unsigned g_keys[NB*NA];
__device__ float4   g_roisAll[NB*NA];
__device__ float4   g_cboxes[NB*NPRE];
__device__ float    g_cscores[NB*NPRE];
__device__ unsigned g_thr[NB];
__device__ int      g_tieneed[NB];
__device__ int      g_ctrG[NB];
__device__ int      g_ctrT[NB];

// ---------------------------------------------------------------------------
// helpers
// ---------------------------------------------------------------------------
__device__ __forceinline__ uint32_t smem_u32(const void* p) {
    uint32_t a;
    asm("{ .reg .u64 t; cvta.to.shared.u64 t, %1; cvt.u32.u64 %0, t; }" : "=r"(a) : "l"(p));
    return a;
}
__device__ __forceinline__ void mma16816(float* c, const uint32_t* a, const uint32_t* b) {
    asm volatile(
        "mma.sync.aligned.m16n8k16.row.col.f32.bf16.bf16.f32 "
        "{%0,%1,%2,%3}, {%4,%5,%6,%7}, {%8,%9}, {%0,%1,%2,%3};"
        : "+f"(c[0]), "+f"(c[1]), "+f"(c[2]), "+f"(c[3])
        : "r"(a[0]), "r"(a[1]), "r"(a[2]), "r"(a[3]), "r"(b[0]), "r"(b[1]));
}
// 3-way bf16 split: h+m+l captures 24 mantissa bits of v
__device__ __forceinline__ void bf16_split3(float v, __nv_bfloat16& h, __nv_bfloat16& m, __nv_bfloat16& l) {
    h = __float2bfloat16_rn(v);
    float r = v - __bfloat162float(h);
    m = __float2bfloat16_rn(r);
    float r2 = r - __bfloat162float(m);
    l = __float2bfloat16_rn(r2);
}

// ---------------------------------------------------------------------------
// Prep A: transpose x [n][c][p] -> g_xb_{h,m,l} [n][p][c] (bf16 3-way split)
// ---------------------------------------------------------------------------
__global__ void transpose_x_kernel(const float* __restrict__ x)
{
    __shared__ float t[32][33];
    const int n  = blockIdx.z;
    const int p0 = blockIdx.x * 32;
    const int c0 = blockIdx.y * 32;
    const int tx = threadIdx.x, ty = threadIdx.y;
#pragma unroll
    for (int j = 0; j < 32; j += 8)
        t[ty + j][tx] = x[((size_t)n * CIN + c0 + ty + j) * NPIX + p0 + tx];
    __syncthreads();
#pragma unroll
    for (int j = 0; j < 32; j += 8) {
        float v = t[tx][ty + j];
        __nv_bfloat16 h, m, l;
        bf16_split3(v, h, m, l);
        size_t o = ((size_t)n * NPIX + p0 + ty + j) * CIN + c0 + tx;
        g_xb_h[o] = h;
        g_xb_m[o] = m;
        g_xb_l[o] = l;
    }
}

// ---------------------------------------------------------------------------
// Prep B: pack w [oc][ic][3][3] -> g_wb_{h,m,l} [tap][oc][ic]
// ---------------------------------------------------------------------------
__global__ void pack_w_kernel(const float* __restrict__ w)
{
    int idx = blockIdx.x * 256 + threadIdx.x;   // oc*512 + ic
    if (idx >= COUT * CIN) return;
    const float* src = w + (size_t)idx * 9;
#pragma unroll
    for (int t = 0; t < 9; t++) {
        __nv_bfloat16 h, m, l;
        bf16_split3(src[t], h, m, l);
        size_t o = (size_t)t * COUT * CIN + idx;
        g_wb_h[o] = h;
        g_wb_m[o] = m;
        g_wb_l[o] = l;
    }
}

// ---------------------------------------------------------------------------
// Conv via bf16x6 m16n8k16 mma with two-level accumulation:
//   acc_main += ah*bh ; acc_corr += am*bm + am*bh + ah*bm + al*bh + ah*bl
// Dropped ml/lm/ll terms are ~2^-26 relative (below fp32 accumulation floor).
// CTA: 256 thr (8 warps, 2x4). Tile 128 oc x 128 px. K: 144 chunks of 32 ic
// (= 2 k16 groups per chunk). Smem rows: 32 bf16 = 16 words, padded to 20
// ((20*grp+qid)%32 hits all 32 banks -> conflict-free fragment LDS).
// ---------------------------------------------------------------------------
#define AST     20
#define TILE_W  (128 * AST)
#define STAGE_W (6 * TILE_W)
#define CONV_SMEM (2 * STAGE_W * 4)   // 122880 B

__device__ __forceinline__ void conv_load_chunk(uint32_t* smw, int c, int s,
                                                int p0, int ocb, int n, int tid)
{
    const int tap = c >> 4;            // 16 chunks of 32 ic per tap
    const int ic0 = (c & 15) << 5;
    const int dy = tap / 3 - 1, dx = tap % 3 - 1;
    uint32_t* st = smw + s * STAGE_W;

    // A tiles: 128 oc x 32 ic bf16, 3 splits. 64B/row = 4x16B per row.
#pragma unroll
    for (int k = 0; k < 2; k++) {
        int cid = tid + k * 256;
        int row = cid >> 2, c16 = cid & 3;
        size_t go = ((size_t)tap * COUT + ocb + row) * CIN + ic0 + c16 * 8;
        uint32_t o = (uint32_t)(row * AST + c16 * 4);
        uint32_t sh = smem_u32(st + 0 * TILE_W + o);
        uint32_t sm_ = smem_u32(st + 1 * TILE_W + o);
        uint32_t sl = smem_u32(st + 2 * TILE_W + o);
        asm volatile("cp.async.cg.shared.global [%0], [%1], 16;" :: "r"(sh),  "l"(g_wb_h + go));
        asm volatile("cp.async.cg.shared.global [%0], [%1], 16;" :: "r"(sm_), "l"(g_wb_m + go));
        asm volatile("cp.async.cg.shared.global [%0], [%1], 16;" :: "r"(sl),  "l"(g_wb_l + go));
    }
    // B tiles: 128 px x 32 ic, shifted, zero-filled at borders, 3 splits
#pragma unroll
    for (int k = 0; k < 2; k++) {
        int cid = tid + k * 256;
        int row = cid >> 2, c16 = cid & 3;
        int p = p0 + row;
        int ys = (p >> 6) + dy, xs = (p & 63) + dx;
        bool valid = ((unsigned)ys < 64u) && ((unsigned)xs < 64u);
        int srow = valid ? (ys * 64 + xs) : 0;
        size_t go = ((size_t)n * NPIX + srow) * CIN + ic0 + c16 * 8;
        unsigned sz = valid ? 16u : 0u;
        uint32_t o = (uint32_t)(row * AST + c16 * 4);
        uint32_t sh = smem_u32(st + 3 * TILE_W + o);
        uint32_t sm_ = smem_u32(st + 4 * TILE_W + o);
        uint32_t sl = smem_u32(st + 5 * TILE_W + o);
        asm volatile("cp.async.cg.shared.global [%0], [%1], 16, %2;" :: "r"(sh),  "l"(g_xb_h + go), "r"(sz));
        asm volatile("cp.async.cg.shared.global [%0], [%1], 16, %2;" :: "r"(sm_), "l"(g_xb_m + go), "r"(sz));
        asm volatile("cp.async.cg.shared.global [%0], [%1], 16, %2;" :: "r"(sl),  "l"(g_xb_l + go), "r"(sz));
    }
    asm volatile("cp.async.commit_group;");
}

__global__ __launch_bounds__(256)
void conv_mma_kernel(const float* __restrict__ bias)
{
    extern __shared__ uint32_t smw[];
    const int tid = threadIdx.x;
    const int p0  = blockIdx.x * 128;
    const int ocb = blockIdx.y * 128;
    const int n   = blockIdx.z;
    const int w   = tid >> 5;
    const int wr  = w >> 2;          // 0..1
    const int wc  = w & 3;           // 0..3
    const int lane = tid & 31;
    const int grp = lane >> 2;       // 0..7
    const int qid = lane & 3;        // 0..3

    float accM[4][4][4];             // hh (main)
    float accC[4][4][4];             // corrections
#pragma unroll
    for (int mt = 0; mt < 4; mt++)
#pragma unroll
        for (int nt = 0; nt < 4; nt++)
#pragma unroll
            for (int q = 0; q < 4; q++) { accM[mt][nt][q] = 0.f; accC[mt][nt][q] = 0.f; }

    conv_load_chunk(smw, 0, 0, p0, ocb, n, tid);

    for (int i = 0; i < 144; i++) {
        const int s = i & 1;
        asm volatile("cp.async.wait_group 0;" ::: "memory");
        __syncthreads();
        if (i + 1 < 144)
            conv_load_chunk(smw, i + 1, s ^ 1, p0, ocb, n, tid);

        const uint32_t* st = smw + s * STAGE_W;
        const uint32_t* Ah = st;
        const uint32_t* Am = st + TILE_W;
        const uint32_t* Al = st + 2 * TILE_W;
        const uint32_t* Bh = st + 3 * TILE_W;
        const uint32_t* Bm = st + 4 * TILE_W;
        const uint32_t* Bl = st + 5 * TILE_W;

#pragma unroll
        for (int ks = 0; ks < 2; ks++) {
            const int kw = ks * 8 + qid;
            uint32_t bfh[4][2], bfm[4][2], bfl[4][2];
#pragma unroll
            for (int nt = 0; nt < 4; nt++) {
                int o = (wc * 32 + nt * 8 + grp) * AST + kw;
                bfh[nt][0] = Bh[o];
                bfh[nt][1] = Bh[o + 4];
                bfm[nt][0] = Bm[o];
                bfm[nt][1] = Bm[o + 4];
                bfl[nt][0] = Bl[o];
                bfl[nt][1] = Bl[o + 4];
            }
            uint32_t afh[4][4], afx[4][4];
            // Phase 1: afx = A_mid. corr: mm, mh, hm. main: hh.
#pragma unroll
            for (int mt = 0; mt < 4; mt++) {
                int r0 = wr * 64 + mt * 16 + grp;
                int o0 = r0 * AST + kw;
                int o1 = (r0 + 8) * AST + kw;
                afh[mt][0] = Ah[o0];
                afh[mt][1] = Ah[o1];
                afh[mt][2] = Ah[o0 + 4];
                afh[mt][3] = Ah[o1 + 4];
                afx[mt][0] = Am[o0];
                afx[mt][1] = Am[o1];
                afx[mt][2] = Am[o0 + 4];
                afx[mt][3] = Am[o1 + 4];
            }
#pragma unroll
            for (int mt = 0; mt < 4; mt++)
#pragma unroll
                for (int nt = 0; nt < 4; nt++) {
                    mma16816(accC[mt][nt], afx[mt], bfm[nt]);   // mm
                    mma16816(accC[mt][nt], afx[mt], bfh[nt]);   // mh
                    mma16816(accC[mt][nt], afh[mt], bfm[nt]);   // hm
                    mma16816(accM[mt][nt], afh[mt], bfh[nt]);   // hh
                }
            // Phase 2: afx = A_low. corr: lh, hl.
#pragma unroll
            for (int mt = 0; mt < 4; mt++) {
                int r0 = wr * 64 + mt * 16 + grp;
                int o0 = r0 * AST + kw;
                int o1 = (r0 + 8) * AST + kw;
                afx[mt][0] = Al[o0];
                afx[mt][1] = Al[o1];
                afx[mt][2] = Al[o0 + 4];
                afx[mt][3] = Al[o1 + 4];
            }
#pragma unroll
            for (int mt = 0; mt < 4; mt++)
#pragma unroll
                for (int nt = 0; nt < 4; nt++) {
                    mma16816(accC[mt][nt], afx[mt], bfh[nt]);   // lh
                    mma16816(accC[mt][nt], afh[mt], bfl[nt]);   // hl
                }
        }
        __syncthreads();
    }

    // epilogue: main + corr + bias, relu, write g_feat [n][oc][px]
#pragma unroll
    for (int mt = 0; mt < 4; mt++) {
        int r0 = ocb + wr * 64 + mt * 16 + grp;
        int r1 = r0 + 8;
        float b0 = bias[r0], b1 = bias[r1];
        float* d0 = g_feat + ((size_t)n * COUT + r0) * NPIX + p0;
        float* d1 = g_feat + ((size_t)n * COUT + r1) * NPIX + p0;
#pragma unroll
        for (int nt = 0; nt < 4; nt++) {
            int col = wc * 32 + nt * 8 + qid * 2;
            float2 v0, v1;
            v0.x = fmaxf((accM[mt][nt][0] + accC[mt][nt][0]) + b0, 0.f);
            v0.y = fmaxf((accM[mt][nt][1] + accC[mt][nt][1]) + b0, 0.f);
            v1.x = fmaxf((accM[mt][nt][2] + accC[mt][nt][2]) + b1, 0.f);
            v1.y = fmaxf((accM[mt][nt][3] + accC[mt][nt][3]) + b1, 0.f);
            *(float2*)(d0 + col) = v0;
            *(float2*)(d1 + col) = v1;
        }
    }
}

// ---------------------------------------------------------------------------
// Kernel 2: fused 1x1 heads
// ---------------------------------------------------------------------------
__global__ __launch_bounds__(256)
void head_kernel(const float* __restrict__ sw, const float* __restrict__ sb,
                 const float* __restrict__ lw, const float* __restrict__ lb,
                 float* __restrict__ d_out)
{
    const int y   = blockIdx.x;
    const int n   = blockIdx.y;
    const int tid = threadIdx.x;
    const int tx  = tid & 15;
    const int ty  = tid >> 4;

    __shared__ float sF[16][64];
    __shared__ float sWc[64][17];

    float acc[4][4];
#pragma unroll
    for (int i = 0; i < 4; i++)
#pragma unroll
        for (int j = 0; j < 4; j++) acc[i][j] = 0.f;

    for (int ic0 = 0; ic0 < CIN; ic0 += 16) {
        for (int i = tid; i < 16 * 64; i += 256) {
            int ic = i >> 6, c = i & 63;
            sF[ic][c] = g_feat[(((size_t)n * CIN + ic0 + ic) * 64 + y) * 64 + c];
        }
        for (int i = tid; i < 64 * 16; i += 256) {
            int o = i >> 4, ic = i & 15;
            float v = 0.f;
            if (o < 36)       v = lw[(size_t)o * CIN + ic0 + ic];
            else if (o < 54)  v = sw[(size_t)(o - 36) * CIN + ic0 + ic];
            sWc[o][ic] = v;
        }
        __syncthreads();
#pragma unroll
        for (int ic = 0; ic < 16; ic++) {
            float a0 = sF[ic][tx * 4 + 0];
            float a1 = sF[ic][tx * 4 + 1];
            float a2 = sF[ic][tx * 4 + 2];
            float a3 = sF[ic][tx * 4 + 3];
#pragma unroll
            for (int oo = 0; oo < 4; oo++) {
                float wv = sWc[ty * 4 + oo][ic];
                acc[oo][0] += a0 * wv;
                acc[oo][1] += a1 * wv;
                acc[oo][2] += a2 * wv;
                acc[oo][3] += a3 * wv;
            }
        }
        __syncthreads();
    }

    const int obase = ty * 4;
#pragma unroll
    for (int oo = 0; oo < 4; oo++) {
        int o = obase + oo;
        if (o < 36) {
            int a = o >> 2, j = o & 3;
            float bias = lb[o];
#pragma unroll
            for (int jj = 0; jj < 4; jj++) {
                int p = y * 64 + tx * 4 + jj;
                d_out[OFF_LOCS + ((size_t)(n * NA + p * 9 + a)) * 4 + j] = acc[oo][jj] + bias;
            }
        } else if (o < 54) {
            int q = o - 36, a = q >> 1, t = q & 1;
            float bias = sb[q];
#pragma unroll
            for (int jj = 0; jj < 4; jj++) {
                int p = y * 64 + tx * 4 + jj;
                d_out[OFF_SCORES + ((size_t)(n * NA + p * 9 + a)) * 2 + t] = acc[oo][jj] + bias;
            }
        }
    }
    if (obase >= 36 && obase < 54) {
#pragma unroll
        for (int pair = 0; pair < 2; pair++) {
            int o = obase + pair * 2;
            if (o < 54) {
                int q = o - 36, a = q >> 1;
                float b0 = sb[q], b1 = sb[q + 1];
#pragma unroll
                for (int jj = 0; jj < 4; jj++) {
                    float s0 = acc[pair * 2][jj] + b0;
                    float s1 = acc[pair * 2 + 1][jj] + b1;
                    float fg = 1.f / (1.f + expf(s0 - s1));
                    int p = y * 64 + tx * 4 + jj;
                    g_fg[(size_t)n * NA + p * 9 + a] = fg;
                }
            }
        }
    }
}

// ---------------------------------------------------------------------------
// Kernel 3: anchors + loc2bbox + clip + min-size + keys
// ---------------------------------------------------------------------------
__global__ void boxes_kernel(const int* __restrict__ imgh, const int* __restrict__ imgw,
                             float* __restrict__ d_out)
{
    int g = blockIdx.x * blockDim.x + threadIdx.x;
    if (g >= NB * NA) return;
    int n = g / NA, i = g % NA;
    int p = i / 9, a = i % 9;
    int r = a / 3, s = a % 3;

    const float rat[3] = {0.5f, 1.f, 2.f};
    const float scl[3] = {8.f, 16.f, 32.f};
    float hh = 16.f * scl[s] * sqrtf(rat[r]);
    float ww = 16.f * scl[s] * sqrtf(1.f / rat[r]);
    float shy = (float)(p >> 6) * 16.f;
    float shx = (float)(p & 63) * 16.f;
    float ay0 = shy + 8.f - 0.5f * hh, ax0 = shx + 8.f - 0.5f * ww;
    float ay1 = shy + 8.f + 0.5f * hh, ax1 = shx + 8.f + 0.5f * ww;

    if (n == 0) {
        d_out[OFF_ANCHOR + (size_t)i * 4 + 0] = ay0;
        d_out[OFF_ANCHOR + (size_t)i * 4 + 1] = ax0;
        d_out[OFF_ANCHOR + (size_t)i * 4 + 2] = ay1;
        d_out[OFF_ANCHOR + (size_t)i * 4 + 3] = ax1;
    }

    float ha = ay1 - ay0, wa = ax1 - ax0;
    float cy = ay0 + 0.5f * ha, cx = ax0 + 0.5f * wa;

    const float* lc = d_out + OFF_LOCS + (size_t)g * 4;
    float dy = lc[0], dx = lc[1], dh = lc[2], dw = lc[3];

    float ncy = dy * ha + cy;
    float ncx = dx * wa + cx;
    float nh  = expf(dh) * ha;
    float nw  = expf(dw) * wa;

    float Hc = (float)(*imgh), Wc = (float)(*imgw);
    float y0 = fminf(fmaxf(ncy - 0.5f * nh, 0.f), Hc);
    float x0 = fminf(fmaxf(ncx - 0.5f * nw, 0.f), Wc);
    float y1 = fminf(fmaxf(ncy + 0.5f * nh, 0.f), Hc);
    float x1 = fminf(fmaxf(ncx + 0.5f * nw, 0.f), Wc);

    float hs = y1 - y0, ws = x1 - x0;
    bool valid = (hs >= 16.f) && (ws >= 16.f);
    float sc = valid ? g_fg[g] : NEG_INF;
    g_msc[g] = sc;

    unsigned u = __float_as_uint(sc);
    u = (u & 0x80000000u) ? ~u : (u | 0x80000000u);
    g_keys[g] = u;
    g_roisAll[g] = make_float4(y0, x0, y1, x1);
}

// ---------------------------------------------------------------------------
// Kernel 4: radix select
// ---------------------------------------------------------------------------
__global__ void radix_kernel()
{
    const int n = blockIdx.x;
    const unsigned* kk = g_keys + (size_t)n * NA;
    __shared__ unsigned hist[256];
    __shared__ unsigned s_prefix;
    __shared__ int s_k;

    unsigned prefix = 0, mask = 0;
    int k = NPRE;

    for (int pass = 0; pass < 4; pass++) {
        int shift = 24 - pass * 8;
        hist[threadIdx.x] = 0;
        __syncthreads();
        for (int i = threadIdx.x; i < NA; i += 256) {
            unsigned u = kk[i];
            if ((u & mask) == prefix) atomicAdd(&hist[(u >> shift) & 255], 1u);
        }
        __syncthreads();
        if (threadIdx.x == 0) {
            int rem = k, d = 255;
            for (; d > 0; d--) {
                int c = (int)hist[d];
                if (rem > c) rem -= c; else break;
            }
            s_prefix = prefix | ((unsigned)d << shift);
            s_k = rem;
        }
        __syncthreads();
        prefix = s_prefix; k = s_k;
        mask |= (0xFFu << shift);
        __syncthreads();
    }
    if (threadIdx.x == 0) {
        g_thr[n] = prefix;
        g_tieneed[n] = k;
        g_ctrG[n] = 0;
        g_ctrT[n] = 0;
    }
}

// ---------------------------------------------------------------------------
// Kernel 5: compact top-6000
// ---------------------------------------------------------------------------
__global__ void compact_kernel()
{
    int g = blockIdx.x * blockDim.x + threadIdx.x;
    if (g >= NB * NA) return;
    int n = g / NA;
    unsigned T = g_thr[n];
    unsigned u = g_keys[g];
    int slot = -1;
    if (u > T) {
        slot = atomicAdd(&g_ctrG[n], 1);
    } else if (u == T) {
        int p2 = atomicAdd(&g_ctrT[n], 1);
        int tn = g_tieneed[n];
        if (p2 < tn) slot = (NPRE - tn) + p2;
    }
    if (slot >= 0) {
        g_cscores[(size_t)n * NPRE + slot] = g_msc[g];
        g_cboxes[(size_t)n * NPRE + slot]  = g_roisAll[g];
    }
}

// ---------------------------------------------------------------------------
// Kernel 6: fixed-iteration NMS
// ---------------------------------------------------------------------------
__global__ __launch_bounds__(1024)
void nms_kernel(float* __restrict__ d_out)
{
    const int n = blockIdx.x;
    const int tid = threadIdx.x;
    __shared__ float ssc[NPRE];
    __shared__ int   skeep[NPOST];
    __shared__ float rv[32];
    __shared__ int   ri[32];
    __shared__ int   sbi;
    __shared__ float sbv;

    const float4* cb = g_cboxes + (size_t)n * NPRE;

    for (int j = tid; j < NPRE; j += 1024) ssc[j] = g_cscores[(size_t)n * NPRE + j];
    __syncthreads();

    for (int it = 0; it < NPOST; it++) {
        float bv = -3e38f; int bi = 0x7FFFFFFF;
        for (int j = tid; j < NPRE; j += 1024) {
            float v = ssc[j];
            if (v > bv) { bv = v; bi = j; }
        }
#pragma unroll
        for (int o = 16; o; o >>= 1) {
            float ov = __shfl_down_sync(0xFFFFFFFFu, bv, o);
            int   oi = __shfl_down_sync(0xFFFFFFFFu, bi, o);
            if (ov > bv || (ov == bv && oi < bi)) { bv = ov; bi = oi; }
        }
        if ((tid & 31) == 0) { rv[tid >> 5] = bv; ri[tid >> 5] = bi; }
        __syncthreads();
        if (tid < 32) {
            bv = rv[tid]; bi = ri[tid];
#pragma unroll
            for (int o = 16; o; o >>= 1) {
                float ov = __shfl_down_sync(0xFFFFFFFFu, bv, o);
                int   oi = __shfl_down_sync(0xFFFFFFFFu, bi, o);
                if (ov > bv || (ov == bv && oi < bi)) { bv = ov; bi = oi; }
            }
            if (tid == 0) { sbi = bi; sbv = bv; }
        }
        __syncthreads();
        const int   idx = sbi;
        const float val = sbv;
        if (tid == 0) skeep[it] = (val > NEG_INF * 0.5f) ? idx : -1;

        float4 B = __ldg((const float4*)&cb[idx]);
        float aB = (B.z - B.x) * (B.w - B.y);

        for (int j = tid; j < NPRE; j += 1024) {
            float4 c = cb[j];
            float tyv = fmaxf(B.x, c.x);
            float txv = fmaxf(B.y, c.y);
            float byv = fminf(B.z, c.z);
            float bxv = fminf(B.w, c.w);
            float ih = fmaxf(byv - tyv, 0.f);
            float iw = fmaxf(bxv - txv, 0.f);
            float inter = ih * iw;
            float a2 = (c.z - c.x) * (c.w - c.y);
            float iou = inter / fmaxf(aB + a2 - inter, 1e-6f);
            if (iou > 0.7f) ssc[j] = NEG_INF;
        }
        if (tid == 0) ssc[idx] = NEG_INF;
        __syncthreads();
    }

    for (int i = tid; i < NPOST; i += 1024) {
        int k2 = skeep[i];
        float4 o = make_float4(0.f, 0.f, 0.f, 0.f);
        if (k2 >= 0) o = cb[k2];
        *(float4*)(d_out + OFF_ROIS + ((size_t)(n * NPOST + i)) * 4) = o;
    }
}

// ---------------------------------------------------------------------------
// launch
// ---------------------------------------------------------------------------
extern "C" void kernel_launch(void* const* d_in, const int* in_sizes, int n_in,
                              void* d_out, int out_size)
{
    const float* x   = (const float*)d_in[0];
    const float* c1w = (const float*)d_in[1];
    const float* c1b = (const float*)d_in[2];
    const float* sw  = (const float*)d_in[3];
    const float* sb  = (const float*)d_in[4];
    const float* lw  = (const float*)d_in[5];
    const float* lb  = (const float*)d_in[6];
    const int*   ih  = (const int*)d_in[7];
    const int*   iw  = (const int*)d_in[8];
    float* out = (float*)d_out;

    cudaFuncSetAttribute(conv_mma_kernel,
                         cudaFuncAttributeMaxDynamicSharedMemorySize, CONV_SMEM);

    transpose_x_kernel<<<dim3(NPIX / 32, CIN / 32, NB), dim3(32, 8)>>>(x);
    pack_w_kernel<<<(COUT * CIN) / 256, 256>>>(c1w);
    conv_mma_kernel<<<dim3(32, 4, NB), 256, CONV_SMEM>>>(c1b);
    head_kernel<<<dim3(HH, NB), 256>>>(sw, sb, lw, lb, out);
    boxes_kernel<<<(NB * NA + 255) / 256, 256>>>(ih, iw, out);
    radix_kernel<<<NB, 256>>>();
    compact_kernel<<<(NB * NA + 255) / 256, 256>>>();
    nms_kernel<<<NB, 1024>>>(out);
}

// round 9
// speedup vs baseline: 2.1528x; 1.3378x over previous
#include <cuda_runtime.h>
#include <cuda_bf16.h>
#include <cuda_fp16.h>
#include <math.h>
#include <stdint.h>

// ---------------------------------------------------------------------------
// Problem constants
// ---------------------------------------------------------------------------
#define NB      4
#define CIN     512
#define COUT    512
#define HH      64
#define WW      64
#define NPIX    (HH*WW)            // 4096
#define NANCH   9
#define NA      (NPIX*NANCH)       // 36864
#define NPRE    6000
#define NPOST   300
#define NEG_INF (-1e30f)

// weight pre-scale (exact power of two)
#define WSCALE      16384.0f
#define WSCALE_INV  6.103515625e-05f

// output layout (flatten of (rpn_locs, rpn_scores, rois, anchor))
#define OFF_LOCS    0
#define OFF_SCORES  (NB*NA*4)                    // 589824
#define OFF_ROIS    (OFF_SCORES + NB*NA*2)       // 884736
#define OFF_ANCHOR  (OFF_ROIS + NB*NPOST*4)      // 889536

// ---------------------------------------------------------------------------
// Device scratch
// ---------------------------------------------------------------------------
__device__ float    g_feat[(size_t)NB*CIN*NPIX];      // 33.5 MB
__device__ __half   g_xh_h[(size_t)NB*NPIX*CIN];
__device__ __half   g_xh_m[(size_t)NB*NPIX*CIN];
__device__ __half   g_wh_h[(size_t)9*COUT*CIN];       // scaled by 2^14
__device__ __half   g_wh_m[(size_t)9*COUT*CIN];       // scaled by 2^14
__device__ float    g_fg[NB*NA];
__device__ float    g_msc[NB*NA];
__device__ unsigned g_keys[NB*NA];
__device__ float4   g_roisAll[NB*NA];
__device__ float4   g_cboxes[NB*NPRE];
__device__ float    g_cscores[NB*NPRE];
__device__ unsigned g_thr[NB];
__device__ int      g_tieneed[NB];
__device__ int      g_ctrG[NB];
__device__ int      g_ctrT[NB];

// ---------------------------------------------------------------------------
// helpers
// ---------------------------------------------------------------------------
__device__ __forceinline__ uint32_t smem_u32(const void* p) {
    uint32_t a;
    asm("{ .reg .u64 t; cvta.to.shared.u64 t, %1; cvt.u32.u64 %0, t; }" : "=r"(a) : "l"(p));
    return a;
}
__device__ __forceinline__ void mma16816h(float* c, const uint32_t* a, const uint32_t* b) {
    asm volatile(
        "mma.sync.aligned.m16n8k16.row.col.f32.f16.f16.f32 "
        "{%0,%1,%2,%3}, {%4,%5,%6,%7}, {%8,%9}, {%0,%1,%2,%3};"
        : "+f"(c[0]), "+f"(c[1]), "+f"(c[2]), "+f"(c[3])
        : "r"(a[0]), "r"(a[1]), "r"(a[2]), "r"(a[3]), "r"(b[0]), "r"(b[1]));
}
// 2-way fp16 split: h+m captures ~22 mantissa bits of v
__device__ __forceinline__ void fp16_split2(float v, __half& h, __half& m) {
    h = __float2half_rn(v);
    float r = v - __half2float(h);
    m = __float2half_rn(r);
}

// ---------------------------------------------------------------------------
// Prep A: transpose x [n][c][p] -> g_xh_{h,m} [n][p][c] (fp16 2-way split)
// ---------------------------------------------------------------------------
__global__ void transpose_x_kernel(const float* __restrict__ x)
{
    __shared__ float t[32][33];
    const int n  = blockIdx.z;
    const int p0 = blockIdx.x * 32;
    const int c0 = blockIdx.y * 32;
    const int tx = threadIdx.x, ty = threadIdx.y;
#pragma unroll
    for (int j = 0; j < 32; j += 8)
        t[ty + j][tx] = x[((size_t)n * CIN + c0 + ty + j) * NPIX + p0 + tx];
    __syncthreads();
#pragma unroll
    for (int j = 0; j < 32; j += 8) {
        float v = t[tx][ty + j];
        __half h, m;
        fp16_split2(v, h, m);
        size_t o = ((size_t)n * NPIX + p0 + ty + j) * CIN + c0 + tx;
        g_xh_h[o] = h;
        g_xh_m[o] = m;
    }
}

// ---------------------------------------------------------------------------
// Prep B: pack w [oc][ic][3][3] -> g_wh_{h,m} [tap][oc][ic], scaled by 2^14
// ---------------------------------------------------------------------------
__global__ void pack_w_kernel(const float* __restrict__ w)
{
    int idx = blockIdx.x * 256 + threadIdx.x;   // oc*512 + ic
    if (idx >= COUT * CIN) return;
    const float* src = w + (size_t)idx * 9;
#pragma unroll
    for (int t = 0; t < 9; t++) {
        __half h, m;
        fp16_split2(src[t] * WSCALE, h, m);
        size_t o = (size_t)t * COUT * CIN + idx;
        g_wh_h[o] = h;
        g_wh_m[o] = m;
    }
}

// ---------------------------------------------------------------------------
// Conv via fp16x3 m16n8k16 mma with two-level accumulation:
//   acc_main += ah*bh ; acc_corr += am*bh + ah*bm     (weights pre-scaled 2^14)
// Residual/dropped terms ~2^-22 relative (x0.87 random-walk) ~ 2e-7 — below
// the ~5e-6 fp32 accumulation floor that R7 passed with.
// CTA: 256 thr (8 warps, 2x4). Tile 128 oc x 128 px. K: 144 chunks of 32 ic.
// Smem rows: 32 fp16 = 16 words padded to 20 (conflict-free fragment LDS).
// ---------------------------------------------------------------------------
#define AST     20
#define TILE_W  (128 * AST)
#define STAGE_W (4 * TILE_W)
#define CONV_SMEM (2 * STAGE_W * 4)   // 81920 B

__device__ __forceinline__ void conv_load_chunk(uint32_t* smw, int c, int s,
                                                int p0, int ocb, int n, int tid)
{
    const int tap = c >> 4;            // 16 chunks of 32 ic per tap
    const int ic0 = (c & 15) << 5;
    const int dy = tap / 3 - 1, dx = tap % 3 - 1;
    uint32_t* st = smw + s * STAGE_W;

    // A tiles: 128 oc x 32 ic fp16, h+m splits
#pragma unroll
    for (int k = 0; k < 2; k++) {
        int cid = tid + k * 256;
        int row = cid >> 2, c16 = cid & 3;
        size_t go = ((size_t)tap * COUT + ocb + row) * CIN + ic0 + c16 * 8;
        uint32_t o = (uint32_t)(row * AST + c16 * 4);
        uint32_t sh = smem_u32(st + 0 * TILE_W + o);
        uint32_t sm_ = smem_u32(st + 1 * TILE_W + o);
        asm volatile("cp.async.cg.shared.global [%0], [%1], 16;" :: "r"(sh),  "l"(g_wh_h + go));
        asm volatile("cp.async.cg.shared.global [%0], [%1], 16;" :: "r"(sm_), "l"(g_wh_m + go));
    }
    // B tiles: 128 px x 32 ic, shifted, zero-filled at borders, h+m splits
#pragma unroll
    for (int k = 0; k < 2; k++) {
        int cid = tid + k * 256;
        int row = cid >> 2, c16 = cid & 3;
        int p = p0 + row;
        int ys = (p >> 6) + dy, xs = (p & 63) + dx;
        bool valid = ((unsigned)ys < 64u) && ((unsigned)xs < 64u);
        int srow = valid ? (ys * 64 + xs) : 0;
        size_t go = ((size_t)n * NPIX + srow) * CIN + ic0 + c16 * 8;
        unsigned sz = valid ? 16u : 0u;
        uint32_t o = (uint32_t)(row * AST + c16 * 4);
        uint32_t sh = smem_u32(st + 2 * TILE_W + o);
        uint32_t sm_ = smem_u32(st + 3 * TILE_W + o);
        asm volatile("cp.async.cg.shared.global [%0], [%1], 16, %2;" :: "r"(sh),  "l"(g_xh_h + go), "r"(sz));
        asm volatile("cp.async.cg.shared.global [%0], [%1], 16, %2;" :: "r"(sm_), "l"(g_xh_m + go), "r"(sz));
    }
    asm volatile("cp.async.commit_group;");
}

__global__ __launch_bounds__(256)
void conv_mma_kernel(const float* __restrict__ bias)
{
    extern __shared__ uint32_t smw[];
    const int tid = threadIdx.x;
    const int p0  = blockIdx.x * 128;
    const int ocb = blockIdx.y * 128;
    const int n   = blockIdx.z;
    const int w   = tid >> 5;
    const int wr  = w >> 2;          // 0..1
    const int wc  = w & 3;           // 0..3
    const int lane = tid & 31;
    const int grp = lane >> 2;       // 0..7
    const int qid = lane & 3;        // 0..3

    float accM[4][4][4];             // hh (main, scaled domain)
    float accC[4][4][4];             // corrections (scaled domain)
#pragma unroll
    for (int mt = 0; mt < 4; mt++)
#pragma unroll
        for (int nt = 0; nt < 4; nt++)
#pragma unroll
            for (int q = 0; q < 4; q++) { accM[mt][nt][q] = 0.f; accC[mt][nt][q] = 0.f; }

    conv_load_chunk(smw, 0, 0, p0, ocb, n, tid);

    for (int i = 0; i < 144; i++) {
        const int s = i & 1;
        asm volatile("cp.async.wait_group 0;" ::: "memory");
        __syncthreads();
        if (i + 1 < 144)
            conv_load_chunk(smw, i + 1, s ^ 1, p0, ocb, n, tid);

        const uint32_t* st = smw + s * STAGE_W;
        const uint32_t* Ah = st;
        const uint32_t* Am = st + TILE_W;
        const uint32_t* Bh = st + 2 * TILE_W;
        const uint32_t* Bm = st + 3 * TILE_W;

#pragma unroll
        for (int ks = 0; ks < 2; ks++) {
            const int kw = ks * 8 + qid;
            uint32_t bfh[4][2], bfm[4][2];
#pragma unroll
            for (int nt = 0; nt < 4; nt++) {
                int o = (wc * 32 + nt * 8 + grp) * AST + kw;
                bfh[nt][0] = Bh[o];
                bfh[nt][1] = Bh[o + 4];
                bfm[nt][0] = Bm[o];
                bfm[nt][1] = Bm[o + 4];
            }
            uint32_t afh[4][4], afm[4][4];
#pragma unroll
            for (int mt = 0; mt < 4; mt++) {
                int r0 = wr * 64 + mt * 16 + grp;
                int o0 = r0 * AST + kw;
                int o1 = (r0 + 8) * AST + kw;
                afh[mt][0] = Ah[o0];
                afh[mt][1] = Ah[o1];
                afh[mt][2] = Ah[o0 + 4];
                afh[mt][3] = Ah[o1 + 4];
                afm[mt][0] = Am[o0];
                afm[mt][1] = Am[o1];
                afm[mt][2] = Am[o0 + 4];
                afm[mt][3] = Am[o1 + 4];
            }
#pragma unroll
            for (int mt = 0; mt < 4; mt++)
#pragma unroll
                for (int nt = 0; nt < 4; nt++) {
                    mma16816h(accC[mt][nt], afm[mt], bfh[nt]);   // mh
                    mma16816h(accC[mt][nt], afh[mt], bfm[nt]);   // hm
                    mma16816h(accM[mt][nt], afh[mt], bfh[nt]);   // hh
                }
        }
        __syncthreads();
    }

    // epilogue: (main + corr) * 2^-14 + bias, relu, write g_feat [n][oc][px]
#pragma unroll
    for (int mt = 0; mt < 4; mt++) {
        int r0 = ocb + wr * 64 + mt * 16 + grp;
        int r1 = r0 + 8;
        float b0 = bias[r0], b1 = bias[r1];
        float* d0 = g_feat + ((size_t)n * COUT + r0) * NPIX + p0;
        float* d1 = g_feat + ((size_t)n * COUT + r1) * NPIX + p0;
#pragma unroll
        for (int nt = 0; nt < 4; nt++) {
            int col = wc * 32 + nt * 8 + qid * 2;
            float2 v0, v1;
            v0.x = fmaxf((accM[mt][nt][0] + accC[mt][nt][0]) * WSCALE_INV + b0, 0.f);
            v0.y = fmaxf((accM[mt][nt][1] + accC[mt][nt][1]) * WSCALE_INV + b0, 0.f);
            v1.x = fmaxf((accM[mt][nt][2] + accC[mt][nt][2]) * WSCALE_INV + b1, 0.f);
            v1.y = fmaxf((accM[mt][nt][3] + accC[mt][nt][3]) * WSCALE_INV + b1, 0.f);
            *(float2*)(d0 + col) = v0;
            *(float2*)(d1 + col) = v1;
        }
    }
}

// ---------------------------------------------------------------------------
// Kernel 2: fused 1x1 heads
// ---------------------------------------------------------------------------
__global__ __launch_bounds__(256)
void head_kernel(const float* __restrict__ sw, const float* __restrict__ sb,
                 const float* __restrict__ lw, const float* __restrict__ lb,
                 float* __restrict__ d_out)
{
    const int y   = blockIdx.x;
    const int n   = blockIdx.y;
    const int tid = threadIdx.x;
    const int tx  = tid & 15;
    const int ty  = tid >> 4;

    __shared__ float sF[16][64];
    __shared__ float sWc[64][17];

    float acc[4][4];
#pragma unroll
    for (int i = 0; i < 4; i++)
#pragma unroll
        for (int j = 0; j < 4; j++) acc[i][j] = 0.f;

    for (int ic0 = 0; ic0 < CIN; ic0 += 16) {
        for (int i = tid; i < 16 * 64; i += 256) {
            int ic = i >> 6, c = i & 63;
            sF[ic][c] = g_feat[(((size_t)n * CIN + ic0 + ic) * 64 + y) * 64 + c];
        }
        for (int i = tid; i < 64 * 16; i += 256) {
            int o = i >> 4, ic = i & 15;
            float v = 0.f;
            if (o < 36)       v = lw[(size_t)o * CIN + ic0 + ic];
            else if (o < 54)  v = sw[(size_t)(o - 36) * CIN + ic0 + ic];
            sWc[o][ic] = v;
        }
        __syncthreads();
#pragma unroll
        for (int ic = 0; ic < 16; ic++) {
            float a0 = sF[ic][tx * 4 + 0];
            float a1 = sF[ic][tx * 4 + 1];
            float a2 = sF[ic][tx * 4 + 2];
            float a3 = sF[ic][tx * 4 + 3];
#pragma unroll
            for (int oo = 0; oo < 4; oo++) {
                float wv = sWc[ty * 4 + oo][ic];
                acc[oo][0] += a0 * wv;
                acc[oo][1] += a1 * wv;
                acc[oo][2] += a2 * wv;
                acc[oo][3] += a3 * wv;
            }
        }
        __syncthreads();
    }

    const int obase = ty * 4;
#pragma unroll
    for (int oo = 0; oo < 4; oo++) {
        int o = obase + oo;
        if (o < 36) {
            int a = o >> 2, j = o & 3;
            float bias = lb[o];
#pragma unroll
            for (int jj = 0; jj < 4; jj++) {
                int p = y * 64 + tx * 4 + jj;
                d_out[OFF_LOCS + ((size_t)(n * NA + p * 9 + a)) * 4 + j] = acc[oo][jj] + bias;
            }
        } else if (o < 54) {
            int q = o - 36, a = q >> 1, t = q & 1;
            float bias = sb[q];
#pragma unroll
            for (int jj = 0; jj < 4; jj++) {
                int p = y * 64 + tx * 4 + jj;
                d_out[OFF_SCORES + ((size_t)(n * NA + p * 9 + a)) * 2 + t] = acc[oo][jj] + bias;
            }
        }
    }
    if (obase >= 36 && obase < 54) {
#pragma unroll
        for (int pair = 0; pair < 2; pair++) {
            int o = obase + pair * 2;
            if (o < 54) {
                int q = o - 36, a = q >> 1;
                float b0 = sb[q], b1 = sb[q + 1];
#pragma unroll
                for (int jj = 0; jj < 4; jj++) {
                    float s0 = acc[pair * 2][jj] + b0;
                    float s1 = acc[pair * 2 + 1][jj] + b1;
                    float fg = 1.f / (1.f + expf(s0 - s1));
                    int p = y * 64 + tx * 4 + jj;
                    g_fg[(size_t)n * NA + p * 9 + a] = fg;
                }
            }
        }
    }
}

// ---------------------------------------------------------------------------
// Kernel 3: anchors + loc2bbox + clip + min-size + keys
// ---------------------------------------------------------------------------
__global__ void boxes_kernel(const int* __restrict__ imgh, const int* __restrict__ imgw,
                             float* __restrict__ d_out)
{
    int g = blockIdx.x * blockDim.x + threadIdx.x;
    if (g >= NB * NA) return;
    int n = g / NA, i = g % NA;
    int p = i / 9, a = i % 9;
    int r = a / 3, s = a % 3;

    const float rat[3] = {0.5f, 1.f, 2.f};
    const float scl[3] = {8.f, 16.f, 32.f};
    float hh = 16.f * scl[s] * sqrtf(rat[r]);
    float ww = 16.f * scl[s] * sqrtf(1.f / rat[r]);
    float shy = (float)(p >> 6) * 16.f;
    float shx = (float)(p & 63) * 16.f;
    float ay0 = shy + 8.f - 0.5f * hh, ax0 = shx + 8.f - 0.5f * ww;
    float ay1 = shy + 8.f + 0.5f * hh, ax1 = shx + 8.f + 0.5f * ww;

    if (n == 0) {
        d_out[OFF_ANCHOR + (size_t)i * 4 + 0] = ay0;
        d_out[OFF_ANCHOR + (size_t)i * 4 + 1] = ax0;
        d_out[OFF_ANCHOR + (size_t)i * 4 + 2] = ay1;
        d_out[OFF_ANCHOR + (size_t)i * 4 + 3] = ax1;
    }

    float ha = ay1 - ay0, wa = ax1 - ax0;
    float cy = ay0 + 0.5f * ha, cx = ax0 + 0.5f * wa;

    const float* lc = d_out + OFF_LOCS + (size_t)g * 4;
    float dy = lc[0], dx = lc[1], dh = lc[2], dw = lc[3];

    float ncy = dy * ha + cy;
    float ncx = dx * wa + cx;
    float nh  = expf(dh) * ha;
    float nw  = expf(dw) * wa;

    float Hc = (float)(*imgh), Wc = (float)(*imgw);
    float y0 = fminf(fmaxf(ncy - 0.5f * nh, 0.f), Hc);
    float x0 = fminf(fmaxf(ncx - 0.5f * nw, 0.f), Wc);
    float y1 = fminf(fmaxf(ncy + 0.5f * nh, 0.f), Hc);
    float x1 = fminf(fmaxf(ncx + 0.5f * nw, 0.f), Wc);

    float hs = y1 - y0, ws = x1 - x0;
    bool valid = (hs >= 16.f) && (ws >= 16.f);
    float sc = valid ? g_fg[g] : NEG_INF;
    g_msc[g] = sc;

    unsigned u = __float_as_uint(sc);
    u = (u & 0x80000000u) ? ~u : (u | 0x80000000u);
    g_keys[g] = u;
    g_roisAll[g] = make_float4(y0, x0, y1, x1);
}

// ---------------------------------------------------------------------------
// Kernel 4: radix select
// ---------------------------------------------------------------------------
__global__ void radix_kernel()
{
    const int n = blockIdx.x;
    const unsigned* kk = g_keys + (size_t)n * NA;
    __shared__ unsigned hist[256];
    __shared__ unsigned s_prefix;
    __shared__ int s_k;

    unsigned prefix = 0, mask = 0;
    int k = NPRE;

    for (int pass = 0; pass < 4; pass++) {
        int shift = 24 - pass * 8;
        hist[threadIdx.x] = 0;
        __syncthreads();
        for (int i = threadIdx.x; i < NA; i += 256) {
            unsigned u = kk[i];
            if ((u & mask) == prefix) atomicAdd(&hist[(u >> shift) & 255], 1u);
        }
        __syncthreads();
        if (threadIdx.x == 0) {
            int rem = k, d = 255;
            for (; d > 0; d--) {
                int c = (int)hist[d];
                if (rem > c) rem -= c; else break;
            }
            s_prefix = prefix | ((unsigned)d << shift);
            s_k = rem;
        }
        __syncthreads();
        prefix = s_prefix; k = s_k;
        mask |= (0xFFu << shift);
        __syncthreads();
    }
    if (threadIdx.x == 0) {
        g_thr[n] = prefix;
        g_tieneed[n] = k;
        g_ctrG[n] = 0;
        g_ctrT[n] = 0;
    }
}

// ---------------------------------------------------------------------------
// Kernel 5: compact top-6000
// ---------------------------------------------------------------------------
__global__ void compact_kernel()
{
    int g = blockIdx.x * blockDim.x + threadIdx.x;
    if (g >= NB * NA) return;
    int n = g / NA;
    unsigned T = g_thr[n];
    unsigned u = g_keys[g];
    int slot = -1;
    if (u > T) {
        slot = atomicAdd(&g_ctrG[n], 1);
    } else if (u == T) {
        int p2 = atomicAdd(&g_ctrT[n], 1);
        int tn = g_tieneed[n];
        if (p2 < tn) slot = (NPRE - tn) + p2;
    }
    if (slot >= 0) {
        g_cscores[(size_t)n * NPRE + slot] = g_msc[g];
        g_cboxes[(size_t)n * NPRE + slot]  = g_roisAll[g];
    }
}

// ---------------------------------------------------------------------------
// Kernel 6: fixed-iteration NMS
// ---------------------------------------------------------------------------
__global__ __launch_bounds__(1024)
void nms_kernel(float* __restrict__ d_out)
{
    const int n = blockIdx.x;
    const int tid = threadIdx.x;
    __shared__ float ssc[NPRE];
    __shared__ int   skeep[NPOST];
    __shared__ float rv[32];
    __shared__ int   ri[32];
    __shared__ int   sbi;
    __shared__ float sbv;

    const float4* cb = g_cboxes + (size_t)n * NPRE;

    for (int j = tid; j < NPRE; j += 1024) ssc[j] = g_cscores[(size_t)n * NPRE + j];
    __syncthreads();

    for (int it = 0; it < NPOST; it++) {
        float bv = -3e38f; int bi = 0x7FFFFFFF;
        for (int j = tid; j < NPRE; j += 1024) {
            float v = ssc[j];
            if (v > bv) { bv = v; bi = j; }
        }
#pragma unroll
        for (int o = 16; o; o >>= 1) {
            float ov = __shfl_down_sync(0xFFFFFFFFu, bv, o);
            int   oi = __shfl_down_sync(0xFFFFFFFFu, bi, o);
            if (ov > bv || (ov == bv && oi < bi)) { bv = ov; bi = oi; }
        }
        if ((tid & 31) == 0) { rv[tid >> 5] = bv; ri[tid >> 5] = bi; }
        __syncthreads();
        if (tid < 32) {
            bv = rv[tid]; bi = ri[tid];
#pragma unroll
            for (int o = 16; o; o >>= 1) {
                float ov = __shfl_down_sync(0xFFFFFFFFu, bv, o);
                int   oi = __shfl_down_sync(0xFFFFFFFFu, bi, o);
                if (ov > bv || (ov == bv && oi < bi)) { bv = ov; bi = oi; }
            }
            if (tid == 0) { sbi = bi; sbv = bv; }
        }
        __syncthreads();
        const int   idx = sbi;
        const float val = sbv;
        if (tid == 0) skeep[it] = (val > NEG_INF * 0.5f) ? idx : -1;

        float4 B = __ldg((const float4*)&cb[idx]);
        float aB = (B.z - B.x) * (B.w - B.y);

        for (int j = tid; j < NPRE; j += 1024) {
            float4 c = cb[j];
            float tyv = fmaxf(B.x, c.x);
            float txv = fmaxf(B.y, c.y);
            float byv = fminf(B.z, c.z);
            float bxv = fminf(B.w, c.w);
            float ih = fmaxf(byv - tyv, 0.f);
            float iw = fmaxf(bxv - txv, 0.f);
            float inter = ih * iw;
            float a2 = (c.z - c.x) * (c.w - c.y);
            float iou = inter / fmaxf(aB + a2 - inter, 1e-6f);
            if (iou > 0.7f) ssc[j] = NEG_INF;
        }
        if (tid == 0) ssc[idx] = NEG_INF;
        __syncthreads();
    }

    for (int i = tid; i < NPOST; i += 1024) {
        int k2 = skeep[i];
        float4 o = make_float4(0.f, 0.f, 0.f, 0.f);
        if (k2 >= 0) o = cb[k2];
        *(float4*)(d_out + OFF_ROIS + ((size_t)(n * NPOST + i)) * 4) = o;
    }
}

// ---------------------------------------------------------------------------
// launch
// ---------------------------------------------------------------------------
extern "C" void kernel_launch(void* const* d_in, const int* in_sizes, int n_in,
                              void* d_out, int out_size)
{
    const float* x   = (const float*)d_in[0];
    const float* c1w = (const float*)d_in[1];
    const float* c1b = (const float*)d_in[2];
    const float* sw  = (const float*)d_in[3];
    const float* sb  = (const float*)d_in[4];
    const float* lw  = (const float*)d_in[5];
    const float* lb  = (const float*)d_in[6];
    const int*   ih  = (const int*)d_in[7];
    const int*   iw  = (const int*)d_in[8];
    float* out = (float*)d_out;

    cudaFuncSetAttribute(conv_mma_kernel,
                         cudaFuncAttributeMaxDynamicSharedMemorySize, CONV_SMEM);

    transpose_x_kernel<<<dim3(NPIX / 32, CIN / 32, NB), dim3(32, 8)>>>(x);
    pack_w_kernel<<<(COUT * CIN) / 256, 256>>>(c1w);
    conv_mma_kernel<<<dim3(32, 4, NB), 256, CONV_SMEM>>>(c1b);
    head_kernel<<<dim3(HH, NB), 256>>>(sw, sb, lw, lb, out);
    boxes_kernel<<<(NB * NA + 255) / 256, 256>>>(ih, iw, out);
    radix_kernel<<<NB, 256>>>();
    compact_kernel<<<(NB * NA + 255) / 256, 256>>>();
    nms_kernel<<<NB, 1024>>>(out);
}